// round 3
// baseline (speedup 1.0000x reference)
#include <cuda_runtime.h>
#include <math.h>

#define BH 32
#define NSEQ 8192
#define DIM 64
#define M 32
#define SCALE 0.125f
#define NCH 16                      /* k_Y chunks per head */

typedef unsigned long long u64;
typedef unsigned int u32;

__device__ float g_KLt[BH * DIM * M];            // [h][k][m]
__device__ float g_Bs[BH * M * M];
__device__ float g_A[(size_t)BH * NSEQ * M];     // 32 MB
__device__ float g_Yp[BH * NCH * M * 65];        // [h][ch][m][d(64)+y1]
__device__ float g_X[BH * M * 65];               // [h][m][d(64)+x1]

__device__ __forceinline__ u64 pk2(float lo, float hi) {
    u64 r; asm("mov.b64 %0, {%1, %2};" : "=l"(r) : "r"(__float_as_uint(lo)), "r"(__float_as_uint(hi))); return r;
}
__device__ __forceinline__ u64 pku(u32 lo, u32 hi) {
    u64 r; asm("mov.b64 %0, {%1, %2};" : "=l"(r) : "r"(lo), "r"(hi)); return r;
}
__device__ __forceinline__ void upk2(u64 v, float& lo, float& hi) {
    u32 a, b; asm("mov.b64 {%0, %1}, %2;" : "=r"(a), "=r"(b) : "l"(v));
    lo = __uint_as_float(a); hi = __uint_as_float(b);
}
__device__ __forceinline__ u64 ffma2(u64 a, u64 b, u64 c) {
    u64 d; asm("fma.rn.f32x2 %0, %1, %2, %3;" : "=l"(d) : "l"(a), "l"(b), "l"(c)); return d;
}

// ---- landmarks + Bs + KLt --------------------------------------------------
__global__ void k_prep(const float* __restrict__ Q, const float* __restrict__ K) {
    int h = blockIdx.x, tid = threadIdx.x;
    __shared__ float sQL[M * 65], sKL[M * 65], sLg[M * 33], sBm[M * 33];
    for (int e = tid; e < M * DIM; e += 128) {
        int m = e >> 6, k = e & 63;
        int idx = (m * (NSEQ - 1)) / (M - 1);
        sKL[m * 65 + k] = K[((size_t)h * NSEQ + idx) * DIM + k] * SCALE;
        sQL[m * 65 + k] = Q[((size_t)h * NSEQ + idx) * DIM + k];
    }
    __syncthreads();
    for (int e = tid; e < M * DIM; e += 128) {
        int m = e & 31, k = e >> 5;
        g_KLt[(h * DIM + k) * M + m] = sKL[m * 65 + k];
    }
    for (int e = tid; e < M * M; e += 128) {
        int i = e >> 5, j = e & 31;
        float s = 0.f;
        #pragma unroll 8
        for (int k = 0; k < DIM; k++) s += sQL[i * 65 + k] * sKL[j * 65 + k];
        sLg[i * 33 + j] = s;
    }
    __syncthreads();
    if (tid < M) {
        int i = tid;
        float mx = -1e30f;
        for (int j = 0; j < M; j++) mx = fmaxf(mx, sLg[i * 33 + j]);
        float s = 0.f;
        for (int j = 0; j < M; j++) { float e2 = __expf(sLg[i * 33 + j] - mx); sBm[i * 33 + j] = e2; s += e2; }
        float r = 1.f / s;
        for (int j = 0; j < M; j++) sBm[i * 33 + j] *= r;
    }
    __syncthreads();
    for (int e = tid; e < M * M; e += 128) {
        int i = e >> 5, j = e & 31;
        g_Bs[h * M * M + e] = 0.5f * (sBm[i * 33 + j] + sBm[j * 33 + i]) + (i == j ? 1e-6f : 0.f);
    }
}

// ---- A = softmax(Q KL^T * s), thread-per-row -------------------------------
__global__ void __launch_bounds__(128) k_A(const float* __restrict__ Q) {
    __shared__ float sQ[128 * 65];
    __shared__ float sKL[DIM * M];
    const int h = blockIdx.y, tile = blockIdx.x, tid = threadIdx.x;
    for (int e = tid; e < DIM * M; e += 128) sKL[e] = g_KLt[h * DIM * M + e];
    const float4* Qg = (const float4*)(Q + ((size_t)h * NSEQ + (size_t)tile * 128) * DIM);
    for (int e4 = tid; e4 < 128 * 16; e4 += 128) {
        float4 v = Qg[e4];
        int n = e4 >> 4, k = (e4 & 15) * 4;
        float* p = sQ + n * 65 + k;
        p[0] = v.x; p[1] = v.y; p[2] = v.z; p[3] = v.w;
    }
    __syncthreads();
    u64 acc[16];
    #pragma unroll
    for (int j = 0; j < 16; j++) acc[j] = 0ull;
    const float* q = sQ + tid * 65;
    #pragma unroll 2
    for (int k = 0; k < DIM; k++) {
        float qv = q[k];
        u64 qd = pk2(qv, qv);
        const uint4* kl = (const uint4*)(sKL + k * M);
        #pragma unroll
        for (int j = 0; j < 8; j++) {
            uint4 b = kl[j];
            acc[2 * j]     = ffma2(qd, pku(b.x, b.y), acc[2 * j]);
            acc[2 * j + 1] = ffma2(qd, pku(b.z, b.w), acc[2 * j + 1]);
        }
    }
    float a[32];
    #pragma unroll
    for (int j = 0; j < 16; j++) upk2(acc[j], a[2 * j], a[2 * j + 1]);
    float mx = a[0];
    #pragma unroll
    for (int j = 1; j < 32; j++) mx = fmaxf(mx, a[j]);
    float s = 0.f;
    #pragma unroll
    for (int j = 0; j < 32; j++) { a[j] = __expf(a[j] - mx); s += a[j]; }
    float r = 1.f / s;
    float4* gA = (float4*)(g_A + ((size_t)h * NSEQ + (size_t)tile * 128 + tid) * M);
    #pragma unroll
    for (int j = 0; j < 8; j++)
        gA[j] = make_float4(a[4 * j] * r, a[4 * j + 1] * r, a[4 * j + 2] * r, a[4 * j + 3] * r);
}

// ---- Y = A^T V + y1 partials, no smem --------------------------------------
__global__ void __launch_bounds__(256) k_Y(const float* __restrict__ V) {
    const int h = blockIdx.y, ch = blockIdx.x;
    const int tid = threadIdx.x, w = tid >> 5, m = tid & 31;
    const int RPC = NSEQ / NCH;  // 512
    const float* Ab = g_A + ((size_t)h * NSEQ + (size_t)ch * RPC) * M + m;
    const float* Vb = V + ((size_t)h * NSEQ + (size_t)ch * RPC) * DIM + w * 8;
    u64 acc[4] = {0ull, 0ull, 0ull, 0ull};
    float y1 = 0.f;
    #pragma unroll 4
    for (int r = 0; r < RPC; r++) {
        float av = Ab[(size_t)r * M];
        uint4 v0 = *(const uint4*)(Vb + (size_t)r * DIM);
        uint4 v1 = *(const uint4*)(Vb + (size_t)r * DIM + 4);
        u64 ad = pk2(av, av);
        acc[0] = ffma2(ad, pku(v0.x, v0.y), acc[0]);
        acc[1] = ffma2(ad, pku(v0.z, v0.w), acc[1]);
        acc[2] = ffma2(ad, pku(v1.x, v1.y), acc[2]);
        acc[3] = ffma2(ad, pku(v1.z, v1.w), acc[3]);
        y1 += av;
    }
    float* yp = g_Yp + ((size_t)(h * NCH + ch) * M + m) * 65;
    #pragma unroll
    for (int p = 0; p < 4; p++) {
        float lo, hi; upk2(acc[p], lo, hi);
        yp[w * 8 + 2 * p] = lo; yp[w * 8 + 2 * p + 1] = hi;
    }
    if (w == 0) yp[64] = y1;
}

// ---- reduce partials + column-parallel pivoted Gauss-Jordan ----------------
__global__ void __launch_bounds__(128) k_solve() {
    const int h = blockIdx.x, c = threadIdx.x;  // columns: 0..31 B, 32..96 [Y|y1]
    __shared__ float sx[M * 128];               // sx[i*128+c]
    if (c < M) {
        for (int i = 0; i < M; i++) sx[i * 128 + c] = g_Bs[h * M * M + i * M + c];
    } else if (c < 97) {
        int d = c - 32;
        for (int i = 0; i < M; i++) {
            float s = 0.f;
            for (int q = 0; q < NCH; q++)
                s += g_Yp[((size_t)(h * NCH + q) * M + i) * 65 + d];
            sx[i * 128 + c] = s;
        }
    }
    for (int k = 0; k < M; k++) {
        __syncthreads();
        // read column k (broadcast), find pivot, capture f[k], f[p]
        float f[M];
        float f_at_k = 0.f;
        #pragma unroll
        for (int i = 0; i < M; i++) f[i] = sx[i * 128 + k];
        int p = k; float best = fabsf(f[k]);
        #pragma unroll
        for (int i = 0; i < M; i++) {
            float v = fabsf(f[i]);
            if (i > k && v > best) { best = v; p = i; }
        }
        float f_at_p = 0.f;
        #pragma unroll
        for (int i = 0; i < M; i++) {
            if (i == k) f_at_k = f[i];
            if (i == p) f_at_p = f[i];
        }
        __syncthreads();
        if (c < 97) {
            // swap rows k,p in this column
            float t = sx[k * 128 + c]; sx[k * 128 + c] = sx[p * 128 + c]; sx[p * 128 + c] = t;
            float inv = 1.f / f_at_p;
            float xk = sx[k * 128 + c] * inv;
            sx[k * 128 + c] = xk;
            #pragma unroll
            for (int i = 0; i < M; i++) {
                if (i == k) continue;
                float fi = (i == p) ? f_at_k : f[i];
                sx[i * 128 + c] -= fi * xk;
            }
        }
    }
    __syncthreads();
    if (c >= 32 && c < 97) {
        for (int i = 0; i < M; i++)
            g_X[(h * M + i) * 65 + (c - 32)] = sx[i * 128 + c];
    }
}

// ---- out = (A X) / max(A x1, 1e-20), thread-per-row ------------------------
__global__ void __launch_bounds__(128) k_pass2(float* __restrict__ out) {
    __shared__ float sX[M * 68];
    __shared__ float sA[128 * 33];
    const int h = blockIdx.y, blk = blockIdx.x, tid = threadIdx.x;
    for (int e = tid; e < M * 65; e += 128) {
        int m = e / 65, d = e % 65;
        sX[m * 68 + d] = g_X[h * M * 65 + e];
    }
    const float4* Ag = (const float4*)(g_A + ((size_t)h * NSEQ + (size_t)blk * 128) * M);
    for (int e4 = tid; e4 < 128 * 8; e4 += 128) {
        float4 v = Ag[e4];
        int rr = e4 >> 3, cc = (e4 & 7) * 4;
        float* p = sA + rr * 33 + cc;
        p[0] = v.x; p[1] = v.y; p[2] = v.z; p[3] = v.w;
    }
    __syncthreads();
    u64 acc[32];
    #pragma unroll
    for (int j = 0; j < 32; j++) acc[j] = 0ull;
    float den = 0.f;
    const float* aRow = sA + tid * 33;
    #pragma unroll 2
    for (int m = 0; m < M; m++) {
        float av = aRow[m];
        u64 ad = pk2(av, av);
        den = fmaf(av, sX[m * 68 + 64], den);
        const uint4* xr = (const uint4*)(sX + m * 68);
        #pragma unroll
        for (int j = 0; j < 16; j++) {
            uint4 b = xr[j];
            acc[2 * j]     = ffma2(ad, pku(b.x, b.y), acc[2 * j]);
            acc[2 * j + 1] = ffma2(ad, pku(b.z, b.w), acc[2 * j + 1]);
        }
    }
    float rinv = 1.f / fmaxf(den, 1e-20f);
    float4* op = (float4*)(out + ((size_t)h * NSEQ + (size_t)blk * 128 + tid) * DIM);
    #pragma unroll
    for (int j = 0; j < 16; j++) {
        float f0, f1, f2, f3;
        upk2(acc[2 * j], f0, f1);
        upk2(acc[2 * j + 1], f2, f3);
        op[j] = make_float4(f0 * rinv, f1 * rinv, f2 * rinv, f3 * rinv);
    }
}

extern "C" void kernel_launch(void* const* d_in, const int* in_sizes, int n_in,
                              void* d_out, int out_size) {
    const float* Q = (const float*)d_in[0];
    const float* K = (const float*)d_in[1];
    const float* V = (const float*)d_in[2];
    float* out = (float*)d_out;
    k_prep<<<BH, 128>>>(Q, K);
    k_A<<<dim3(NSEQ / 128, BH), 128>>>(Q);
    k_Y<<<dim3(NCH, BH), 256>>>(V);
    k_solve<<<BH, 128>>>();
    k_pass2<<<dim3(NSEQ / 128, BH), 128>>>(out);
}

// round 5
// speedup vs baseline: 1.3429x; 1.3429x over previous
#include <cuda_runtime.h>
#include <math.h>

#define BH 32
#define NSEQ 8192
#define DIM 64
#define M 32
#define SCALE 0.125f
#define NCH 16

typedef unsigned long long u64;
typedef unsigned int u32;

__device__ float g_KLt[BH * DIM * M];                 // [h][k][m]
__device__ float g_Bs[BH * M * M];
__device__ float g_A[(size_t)BH * NSEQ * M];          // 32 MB
__device__ float g_Yp[(size_t)BH * NCH * 8 * 66 * M]; // [h][c][w][dslot66][m]
__device__ float g_Y[BH * M * 65];                    // [h][m][d:64 + y1]
__device__ float g_X[BH * M * 65];                    // [h][m][d:64 + x1]

__device__ __forceinline__ u64 pk2(float lo, float hi) {
    u64 r; asm("mov.b64 %0, {%1, %2};" : "=l"(r) : "r"(__float_as_uint(lo)), "r"(__float_as_uint(hi))); return r;
}
__device__ __forceinline__ u64 pku(u32 lo, u32 hi) {
    u64 r; asm("mov.b64 %0, {%1, %2};" : "=l"(r) : "r"(lo), "r"(hi)); return r;
}
__device__ __forceinline__ void upk2(u64 v, float& lo, float& hi) {
    u32 a, b; asm("mov.b64 {%0, %1}, %2;" : "=r"(a), "=r"(b) : "l"(v));
    lo = __uint_as_float(a); hi = __uint_as_float(b);
}
__device__ __forceinline__ u64 ffma2(u64 a, u64 b, u64 c) {
    u64 d; asm("fma.rn.f32x2 %0, %1, %2, %3;" : "=l"(d) : "l"(a), "l"(b), "l"(c)); return d;
}

// ---- landmarks + Bs + KLt --------------------------------------------------
__global__ void k_prep(const float* __restrict__ Q, const float* __restrict__ K) {
    int h = blockIdx.x, tid = threadIdx.x;
    __shared__ float sQL[M * 65], sKL[M * 65], sLg[M * 33], sBm[M * 33];
    for (int e = tid; e < M * DIM; e += 128) {
        int m = e >> 6, k = e & 63;
        int idx = (m * (NSEQ - 1)) / (M - 1);
        sKL[m * 65 + k] = K[((size_t)h * NSEQ + idx) * DIM + k] * SCALE;
        sQL[m * 65 + k] = Q[((size_t)h * NSEQ + idx) * DIM + k];
    }
    __syncthreads();
    for (int e = tid; e < M * DIM; e += 128) {
        int m = e & 31, k = e >> 5;
        g_KLt[(h * DIM + k) * M + m] = sKL[m * 65 + k];
    }
    for (int e = tid; e < M * M; e += 128) {
        int i = e >> 5, j = e & 31;
        float s = 0.f;
        #pragma unroll 8
        for (int k = 0; k < DIM; k++) s += sQL[i * 65 + k] * sKL[j * 65 + k];
        sLg[i * 33 + j] = s;
    }
    __syncthreads();
    if (tid < M) {
        int i = tid;
        float mx = -1e30f;
        for (int j = 0; j < M; j++) mx = fmaxf(mx, sLg[i * 33 + j]);
        float s = 0.f;
        for (int j = 0; j < M; j++) { float e2 = __expf(sLg[i * 33 + j] - mx); sBm[i * 33 + j] = e2; s += e2; }
        float r = 1.f / s;
        for (int j = 0; j < M; j++) sBm[i * 33 + j] *= r;
    }
    __syncthreads();
    for (int e = tid; e < M * M; e += 128) {
        int i = e >> 5, j = e & 31;
        g_Bs[h * M * M + e] = 0.5f * (sBm[i * 33 + j] + sBm[j * 33 + i]) + (i == j ? 1e-6f : 0.f);
    }
}

// ---- A = softmax(Q KL^T * s), 2 rows/thread, 256-row tiles -----------------
#define KA_SMEM ((256 * 65 + DIM * M) * 4)
__global__ void __launch_bounds__(128) k_A(const float* __restrict__ Q) {
    extern __shared__ float sm[];
    float* sQ = sm;
    float* sKL = sm + 256 * 65;
    const int h = blockIdx.y, tile = blockIdx.x, tid = threadIdx.x;
    for (int e = tid; e < DIM * M; e += 128) sKL[e] = g_KLt[h * DIM * M + e];
    const float4* Qg = (const float4*)(Q + ((size_t)h * NSEQ + (size_t)tile * 256) * DIM);
    for (int e4 = tid; e4 < 256 * 16; e4 += 128) {
        float4 v = Qg[e4];
        int n = e4 >> 4, k = (e4 & 15) * 4;
        float* p = sQ + n * 65 + k;
        p[0] = v.x; p[1] = v.y; p[2] = v.z; p[3] = v.w;
    }
    __syncthreads();
    u64 acc0[16], acc1[16];
    #pragma unroll
    for (int j = 0; j < 16; j++) { acc0[j] = 0ull; acc1[j] = 0ull; }
    const float* q0 = sQ + tid * 65;
    const float* q1 = sQ + (tid + 128) * 65;
    #pragma unroll 2
    for (int k = 0; k < DIM; k++) {
        float qa = q0[k], qb = q1[k];
        u64 da = pk2(qa, qa), db = pk2(qb, qb);
        const uint4* kl = (const uint4*)(sKL + k * M);
        #pragma unroll
        for (int j = 0; j < 8; j++) {
            uint4 b = kl[j];
            u64 b0 = pku(b.x, b.y), b1 = pku(b.z, b.w);
            acc0[2 * j]     = ffma2(da, b0, acc0[2 * j]);
            acc0[2 * j + 1] = ffma2(da, b1, acc0[2 * j + 1]);
            acc1[2 * j]     = ffma2(db, b0, acc1[2 * j]);
            acc1[2 * j + 1] = ffma2(db, b1, acc1[2 * j + 1]);
        }
    }
    for (int r = 0; r < 2; r++) {
        u64* acc = r ? acc1 : acc0;
        float a[32];
        #pragma unroll
        for (int j = 0; j < 16; j++) upk2(acc[j], a[2 * j], a[2 * j + 1]);
        float mx = a[0];
        #pragma unroll
        for (int j = 1; j < 32; j++) mx = fmaxf(mx, a[j]);
        float s = 0.f;
        #pragma unroll
        for (int j = 0; j < 32; j++) { a[j] = __expf(a[j] - mx); s += a[j]; }
        float rc = 1.f / s;
        float4* gA = (float4*)(g_A + ((size_t)h * NSEQ + (size_t)tile * 256 + tid + r * 128) * M);
        #pragma unroll
        for (int j = 0; j < 8; j++)
            gA[j] = make_float4(a[4 * j] * rc, a[4 * j + 1] * rc, a[4 * j + 2] * rc, a[4 * j + 3] * rc);
    }
}

// ---- Y partials: warp-per-row-stripe, m-pairs from A uint4 -----------------
__global__ void __launch_bounds__(256) k_Y(const float* __restrict__ V) {
    const int h = blockIdx.y, ch = blockIdx.x;
    const int tid = threadIdx.x, w = tid >> 5, l = tid & 31;
    const int RPC = NSEQ / NCH;  // 512
    const float* Ab = g_A + ((size_t)h * NSEQ + (size_t)ch * RPC) * M;
    const float* Vb = V + ((size_t)h * NSEQ + (size_t)ch * RPC) * DIM;
    u64 acc[16][2], y1[16];
    #pragma unroll
    for (int j = 0; j < 16; j++) { acc[j][0] = 0ull; acc[j][1] = 0ull; y1[j] = 0ull; }
    const u64 ONE2 = pk2(1.f, 1.f);
    for (int r = w; r < RPC; r += 8) {
        const uint4* arow = (const uint4*)(Ab + (size_t)r * M);
        u64 vp = *(const u64*)(Vb + (size_t)r * DIM + 2 * l);
        float vlo, vhi; upk2(vp, vlo, vhi);
        u64 v0 = pk2(vlo, vlo), v1 = pk2(vhi, vhi);
        #pragma unroll
        for (int j = 0; j < 8; j++) {
            uint4 a4 = arow[j];
            u64 ap0 = pku(a4.x, a4.y), ap1 = pku(a4.z, a4.w);
            acc[2 * j][0]     = ffma2(ap0, v0, acc[2 * j][0]);
            acc[2 * j][1]     = ffma2(ap0, v1, acc[2 * j][1]);
            acc[2 * j + 1][0] = ffma2(ap1, v0, acc[2 * j + 1][0]);
            acc[2 * j + 1][1] = ffma2(ap1, v1, acc[2 * j + 1][1]);
            y1[2 * j]     = ffma2(ap0, ONE2, y1[2 * j]);
            y1[2 * j + 1] = ffma2(ap1, ONE2, y1[2 * j + 1]);
        }
    }
    float* yp = g_Yp + (((size_t)(h * NCH + ch) * 8 + w) * 66) * M;
    #pragma unroll
    for (int mp = 0; mp < 16; mp++) {
        *(u64*)(yp + (2 * l + 0) * M + 2 * mp) = acc[mp][0];
        *(u64*)(yp + (2 * l + 1) * M + 2 * mp) = acc[mp][1];
    }
    if (l == 0) {
        #pragma unroll
        for (int mp = 0; mp < 16; mp++)
            *(u64*)(yp + 64 * M + 2 * mp) = y1[mp];
    }
}

// ---- reduce 128 partials per (m,d) -----------------------------------------
__global__ void __launch_bounds__(1024) k_red() {
    const int h = blockIdx.x, tid = threadIdx.x;
    const int m = tid & 31, dg = tid >> 5;
    const float* base = g_Yp + (size_t)h * NCH * 8 * 66 * M;
    for (int d = dg; d < 65; d += 32) {
        float s = 0.f;
        #pragma unroll 4
        for (int cw = 0; cw < NCH * 8; cw++)
            s += base[((size_t)cw * 66 + d) * M + m];
        g_Y[(h * M + m) * 65 + d] = s;
    }
}

// ---- pivoted Gauss-Jordan, warp pivot search -------------------------------
__global__ void __launch_bounds__(128) k_solve() {
    const int h = blockIdx.x, c = threadIdx.x;  // cols: 0..31 B, 32..96 [Y|y1]
    __shared__ float sx[M * 97];
    __shared__ float sf[M];
    __shared__ int sp;
    if (c < M) {
        for (int i = 0; i < M; i++) sx[i * 97 + c] = g_Bs[h * M * M + i * M + c];
    } else if (c < 97) {
        int d = c - 32;
        for (int i = 0; i < M; i++) sx[i * 97 + c] = g_Y[(h * M + i) * 65 + d];
    }
    __syncthreads();
    for (int k = 0; k < M; k++) {
        if (c < 32) {
            float v = (c >= k) ? fabsf(sx[c * 97 + k]) : -1.f;
            int bi = c;
            #pragma unroll
            for (int o = 16; o; o >>= 1) {
                float ov = __shfl_xor_sync(~0u, v, o);
                int oi = __shfl_xor_sync(~0u, bi, o);
                if (ov > v) { v = ov; bi = oi; }
            }
            if (c == 0) sp = bi;
        }
        __syncthreads();
        int p = sp;
        if (c < 97 && p != k) {
            float t = sx[k * 97 + c]; sx[k * 97 + c] = sx[p * 97 + c]; sx[p * 97 + c] = t;
        }
        __syncthreads();
        if (c < 32) sf[c] = sx[c * 97 + k];
        __syncthreads();
        if (c < 97) {
            float inv = 1.f / sf[k];
            float xk = sx[k * 97 + c] * inv;
            sx[k * 97 + c] = xk;
            #pragma unroll
            for (int i = 0; i < M; i++) {
                if (i == k) continue;
                sx[i * 97 + c] = fmaf(-sf[i], xk, sx[i * 97 + c]);
            }
        }
        __syncthreads();
    }
    if (c >= 32 && c < 97) {
        for (int i = 0; i < M; i++)
            g_X[(h * M + i) * 65 + (c - 32)] = sx[i * 97 + c];
    }
}

// ---- out = (A X) / max(A x1, 1e-20): 1 row x 32 cols per thread ------------
__global__ void __launch_bounds__(256) k_pass2(float* __restrict__ out) {
    __shared__ float sX[M * 68];
    __shared__ float sA[128 * 33];
    const int h = blockIdx.y, blk = blockIdx.x, tid = threadIdx.x;
    for (int e = tid; e < M * 65; e += 256) {
        int m = e / 65, d = e % 65;
        sX[m * 68 + d] = g_X[h * M * 65 + e];
    }
    const float4* Ag = (const float4*)(g_A + ((size_t)h * NSEQ + (size_t)blk * 128) * M);
    for (int e4 = tid; e4 < 128 * 8; e4 += 256) {
        float4 v = Ag[e4];
        int rr = e4 >> 3, cc = (e4 & 7) * 4;
        float* p = sA + rr * 33 + cc;
        p[0] = v.x; p[1] = v.y; p[2] = v.z; p[3] = v.w;
    }
    __syncthreads();
    const int row = tid >> 1, half = tid & 1;  // 128 rows x 2 column-halves
    u64 acc[16];
    #pragma unroll
    for (int j = 0; j < 16; j++) acc[j] = 0ull;
    float den = 0.f;
    const float* ap = sA + row * 33;
    const float* xh = sX + 32 * half;
    #pragma unroll 2
    for (int m = 0; m < M; m++) {
        float av = ap[m];
        den = fmaf(av, sX[m * 68 + 64], den);
        u64 ad = pk2(av, av);
        const uint4* xr = (const uint4*)(xh + m * 68);
        #pragma unroll
        for (int j = 0; j < 8; j++) {
            uint4 b = xr[j];
            acc[2 * j]     = ffma2(ad, pku(b.x, b.y), acc[2 * j]);
            acc[2 * j + 1] = ffma2(ad, pku(b.z, b.w), acc[2 * j + 1]);
        }
    }
    float rinv = 1.f / fmaxf(den, 1e-20f);
    float4* op = (float4*)(out + ((size_t)h * NSEQ + (size_t)blk * 128 + row) * DIM + 32 * half);
    #pragma unroll
    for (int j = 0; j < 8; j++) {
        float f0, f1, f2, f3;
        upk2(acc[2 * j], f0, f1);
        upk2(acc[2 * j + 1], f2, f3);
        op[j] = make_float4(f0 * rinv, f1 * rinv, f2 * rinv, f3 * rinv);
    }
}

extern "C" void kernel_launch(void* const* d_in, const int* in_sizes, int n_in,
                              void* d_out, int out_size) {
    const float* Q = (const float*)d_in[0];
    const float* K = (const float*)d_in[1];
    const float* V = (const float*)d_in[2];
    float* out = (float*)d_out;
    cudaFuncSetAttribute(k_A, cudaFuncAttributeMaxDynamicSharedMemorySize, KA_SMEM);
    k_prep<<<BH, 128>>>(Q, K);
    k_A<<<dim3(NSEQ / 256, BH), 128, KA_SMEM>>>(Q);
    k_Y<<<dim3(NCH, BH), 256>>>(V);
    k_red<<<BH, 1024>>>();
    k_solve<<<BH, 128>>>();
    k_pass2<<<dim3(NSEQ / 128, BH), 256>>>(out);
}